// round 2
// baseline (speedup 1.0000x reference)
#include <cuda_runtime.h>
#include <math.h>

// Problem dims (fixed per reference setup_inputs)
#define NTOK 16384   // B*T = 8*2048
#define DDIM 256
#define VDIM 8192
#define TVAL 2048

// Tiling for argmin GEMM
#define TM 64
#define TV 128
#define TPB 256
#define XS_STRIDE 68   // padded k-major stride (16B-aligned, conflict-light)

// Output layout (concatenated flattened, float32):
//   quantize [8,2048,256] -> 4,194,304
//   codes    [8,2048]     ->    16,384
//   new_embed[8192,256]   -> 2,097,152
//   new_cs   [8192]       ->     8,192
//   new_ea   [8192,256]   -> 2,097,152
#define OFF_Q    0
#define OFF_CODE 4194304
#define OFF_NE   4210688
#define OFF_NCS  6307840
#define OFF_NEA  6316032

// Scratch (no allocations allowed -> device globals)
__device__ float g_sums[VDIM * DDIM];
__device__ float g_counts[VDIM];
__device__ float g_en2[VDIM];     // 0.5 * ||e_v||^2
__device__ int   g_codes[NTOK];

// ---------------------------------------------------------------------------
// 0.5*||e||^2 per codebook row (one warp per row)
__global__ void en2_kernel(const float* __restrict__ embed) {
    int warp = (blockIdx.x * blockDim.x + threadIdx.x) >> 5;
    int lane = threadIdx.x & 31;
    if (warp >= VDIM) return;
    const float* row = embed + (size_t)warp * DDIM;
    float s = 0.f;
#pragma unroll
    for (int j = 0; j < 8; j++) {
        float x = row[lane + 32 * j];
        s += x * x;
    }
#pragma unroll
    for (int o = 16; o; o >>= 1) s += __shfl_xor_sync(0xffffffffu, s, o);
    if (lane == 0) g_en2[warp] = 0.5f * s;
}

// Zero the EMA scratch each launch (graph replays must be deterministic)
__global__ void zero_kernel() {
    int i = blockIdx.x * blockDim.x + threadIdx.x;
    int stride = gridDim.x * blockDim.x;
    for (int idx = i; idx < VDIM * DDIM; idx += stride) g_sums[idx] = 0.f;
    for (int idx = i; idx < VDIM; idx += stride) g_counts[idx] = 0.f;
}

// ---------------------------------------------------------------------------
// Fused distance-GEMM + argmin.
// score(t,v) = 0.5*||e_v||^2 - x_t . e_v   (same argmin as squared distance)
// CTA: 64 tokens x full V sweep in tiles of 128 codes. 256 threads,
// thread tile 4 tokens x 8 codes, fp32 accumulation.
__global__ __launch_bounds__(TPB, 1)
void argmin_kernel(const float* __restrict__ input,
                   const float* __restrict__ embed) {
    extern __shared__ float sm[];
    float* xs   = sm;                           // [256][XS_STRIDE]  k-major x
    float* es   = sm + 256 * XS_STRIDE;         // [TV][256] swizzled e tile
    float* sen2 = es + TV * DDIM;               // [TV]
    // argmin reduction arrays reuse es space after the mainloop
    float* redv = es;                           // [TM][16]
    int*   redi = (int*)(es + TM * 16);         // [TM][16]

    const int tid   = threadIdx.x;
    const int tBase = blockIdx.x * TM;

    // Stage x tile transposed: xs[k][t] = input[tBase+t][k]
    for (int idx = tid; idx < TM * (DDIM / 4); idx += TPB) {
        int t = idx >> 6;          // 0..63
        int c = idx & 63;          // float4 chunk along k
        float4 v = *(const float4*)(input + (size_t)(tBase + t) * DDIM + 4 * c);
        int k = 4 * c;
        xs[(k + 0) * XS_STRIDE + t] = v.x;
        xs[(k + 1) * XS_STRIDE + t] = v.y;
        xs[(k + 2) * XS_STRIDE + t] = v.z;
        xs[(k + 3) * XS_STRIDE + t] = v.w;
    }

    const int tx = tid & 15;   // code-column group
    const int ty = tid >> 4;   // token-row group
    const int t0 = ty * 4;

    float bestV[4];
    int   bestI[4];
#pragma unroll
    for (int i = 0; i < 4; i++) { bestV[i] = 3.4e38f; bestI[i] = 0; }

    for (int vBase = 0; vBase < VDIM; vBase += TV) {
        __syncthreads();  // previous tile fully consumed (also covers xs stores)

        // Stage e tile with 4-bit XOR chunk swizzle: es[r][4*(c ^ (r&15)) + ...]
        for (int idx = tid; idx < TV * (DDIM / 4); idx += TPB) {
            int r = idx >> 6;
            int c = idx & 63;
            float4 v = *(const float4*)(embed + (size_t)(vBase + r) * DDIM + 4 * c);
            int cs = c ^ (r & 15);
            *(float4*)(es + r * DDIM + 4 * cs) = v;
        }
        if (tid < TV) sen2[tid] = g_en2[vBase + tid];
        __syncthreads();

        float acc[4][8];
#pragma unroll
        for (int i = 0; i < 4; i++)
#pragma unroll
            for (int j = 0; j < 8; j++) acc[i][j] = 0.f;

#pragma unroll 2
        for (int k = 0; k < DDIM; k += 4) {
            int c = k >> 2;
            float xf[4][4];  // [kk][token]
#pragma unroll
            for (int kk = 0; kk < 4; kk++) {
                float4 xv = *(const float4*)(xs + (k + kk) * XS_STRIDE + t0);
                xf[kk][0] = xv.x; xf[kk][1] = xv.y;
                xf[kk][2] = xv.z; xf[kk][3] = xv.w;
            }
#pragma unroll
            for (int jj = 0; jj < 8; jj++) {
                int vl = tx + 16 * jj;
                // (vl & 15) == tx, so swizzled chunk is c ^ tx
                float4 ev = *(const float4*)(es + vl * DDIM + 4 * (c ^ tx));
#pragma unroll
                for (int i = 0; i < 4; i++) {
                    acc[i][jj] += xf[0][i] * ev.x + xf[1][i] * ev.y
                                + xf[2][i] * ev.z + xf[3][i] * ev.w;
                }
            }
        }

        // Tile epilogue: running per-thread argmin
#pragma unroll
        for (int jj = 0; jj < 8; jj++) {
            int vl = tx + 16 * jj;
            float h = sen2[vl];
            int gv = vBase + vl;
#pragma unroll
            for (int i = 0; i < 4; i++) {
                float s = h - acc[i][jj];
                if (s < bestV[i] || (s == bestV[i] && gv < bestI[i])) {
                    bestV[i] = s; bestI[i] = gv;
                }
            }
        }
    }

    // Cross-thread reduction over the 16 code-column groups
    __syncthreads();
#pragma unroll
    for (int i = 0; i < 4; i++) {
        redv[(t0 + i) * 16 + tx] = bestV[i];
        redi[(t0 + i) * 16 + tx] = bestI[i];
    }
    __syncthreads();
    if (tid < TM) {
        float bv = redv[tid * 16];
        int   bi = redi[tid * 16];
        for (int j = 1; j < 16; j++) {
            float v = redv[tid * 16 + j];
            int   ii = redi[tid * 16 + j];
            if (v < bv || (v == bv && ii < bi)) { bv = v; bi = ii; }
        }
        g_codes[tBase + tid] = bi;
    }
}

// ---------------------------------------------------------------------------
// Per-token: write quantize (= embed[code]), codes (as float), and scatter
// the EMA sums/counts with atomics.
__global__ void scatter_kernel(const float* __restrict__ input,
                               const float* __restrict__ embed,
                               float* __restrict__ out) {
    int t = blockIdx.x;
    int d = threadIdx.x;
    int c = g_codes[t];
    float e = embed[(size_t)c * DDIM + d];
    out[OFF_Q + (size_t)t * DDIM + d] = e;
    atomicAdd(&g_sums[(size_t)c * DDIM + d], input[(size_t)t * DDIM + d]);
    if (d == 0) {
        atomicAdd(&g_counts[c], 1.0f);
        out[OFF_CODE + t] = (float)c;
    }
}

// EMA finalize: new_cluster_size, new_embed_avg, new_embed
__global__ void finalize_kernel(const float* __restrict__ cluster_size,
                                const float* __restrict__ embed_avg,
                                float* __restrict__ out) {
    int idx = blockIdx.x * blockDim.x + threadIdx.x;
    if (idx >= VDIM * DDIM) return;
    int v = idx >> 8;
    float ncs = cluster_size[v] * 0.99f + g_counts[v] * 0.01f;
    float avg = embed_avg[idx] * 0.99f + (g_sums[idx] * (1.0f / TVAL)) * 0.01f;
    out[OFF_NEA + idx] = avg;
    out[OFF_NE + idx]  = avg / (ncs + 1e-5f);
    if ((idx & 255) == 0) out[OFF_NCS + v] = ncs;
}

// ---------------------------------------------------------------------------
extern "C" void kernel_launch(void* const* d_in, const int* in_sizes, int n_in,
                              void* d_out, int out_size) {
    const float* input        = (const float*)d_in[0];  // [8,2048,256]
    const float* embed        = (const float*)d_in[1];  // [8192,256]
    const float* cluster_size = (const float*)d_in[2];  // [8192]
    const float* embed_avg    = (const float*)d_in[3];  // [8192,256]
    float* out = (float*)d_out;

    const int smem = (256 * XS_STRIDE + TV * DDIM + TV) * sizeof(float);
    cudaFuncSetAttribute(argmin_kernel,
                         cudaFuncAttributeMaxDynamicSharedMemorySize, smem);

    en2_kernel<<<VDIM / 8, 256>>>(embed);
    zero_kernel<<<2048, 256>>>();
    argmin_kernel<<<NTOK / TM, TPB, smem>>>(input, embed);
    scatter_kernel<<<NTOK, DDIM>>>(input, embed, out);
    finalize_kernel<<<(VDIM * DDIM + 255) / 256, 256>>>(cluster_size, embed_avg, out);
}

// round 4
// speedup vs baseline: 2.0126x; 2.0126x over previous
#include <cuda_runtime.h>
#include <cuda_bf16.h>
#include <cstdint>

// Problem dims (fixed per reference setup_inputs)
#define NTOK 16384   // B*T
#define DDIM 256
#define VDIM 8192
#define TVAL 2048
#define KBIG 1024    // 4-term bf16 split: [xh|xh|xl|xl] . [eh|el|eh|el]

// Argmin GEMM tiling
#define TM 64        // tokens per CTA
#define TN 128       // codes per N-tile
#define KCH 64       // K per streamed chunk
#define NCHUNK (KBIG / KCH)   // 16
#define NTILES (VDIM / TN)    // 64
#define TPB 256               // 8 warps: 2 (M) x 4 (N), warp tile 32x32

// Smem layout (bytes)
#define A_PAD 1032            // 1024 + 8 elems -> 2064B row stride (conflict-free)
#define A_STRIDE (A_PAD * 2)  // 2064
#define B_PAD 72              // 64 + 8 elems -> 144B row stride (conflict-free)
#define B_STRIDE (B_PAD * 2)  // 144
#define SM_A 0
#define SM_B (TM * A_STRIDE)               // 132096
#define B_BUF (TN * B_STRIDE)              // 18432
#define SM_EN2 (SM_B + 3 * B_BUF)          // 187392
#define SM_RED (SM_EN2 + TN * 4)           // 187904
#define SM_TOTAL (SM_RED + TM * 4 * 8)     // 189952

// Output layout (concatenated flattened, float32)
#define OFF_Q    0
#define OFF_CODE 4194304
#define OFF_NE   4210688
#define OFF_NCS  6307840
#define OFF_NEA  6316032

// ---------------------------------------------------------------------------
// Device scratch (no allocations allowed)
__device__ __nv_bfloat16 g_Abig[(size_t)NTOK * KBIG];
__device__ __nv_bfloat16 g_Bbig[(size_t)VDIM * KBIG];
__device__ float g_sums[VDIM * DDIM];
__device__ float g_counts[VDIM];
__device__ float g_en2[VDIM];
__device__ int   g_codes[NTOK];

// ---------------------------------------------------------------------------
__device__ __forceinline__ uint32_t smem_u32(const void* p) {
    uint32_t a;
    asm("{ .reg .u64 t; cvta.to.shared.u64 t, %1; cvt.u32.u64 %0, t; }"
        : "=r"(a) : "l"(p));
    return a;
}
__device__ __forceinline__ void cp16(uint32_t dst, const void* src) {
    asm volatile("cp.async.cg.shared.global [%0], [%1], 16;"
                 :: "r"(dst), "l"(src) : "memory");
}
#define CP_COMMIT() asm volatile("cp.async.commit_group;" ::: "memory")
#define CP_WAIT(n)  asm volatile("cp.async.wait_group %0;" :: "n"(n) : "memory")

__device__ __forceinline__ void ldmx4(uint32_t (&r)[4], uint32_t addr) {
    asm volatile("ldmatrix.sync.aligned.m8n8.x4.shared.b16 {%0,%1,%2,%3}, [%4];"
                 : "=r"(r[0]), "=r"(r[1]), "=r"(r[2]), "=r"(r[3]) : "r"(addr));
}
__device__ __forceinline__ void mma16816(float (&d)[4], const uint32_t (&a)[4],
                                         uint32_t b0, uint32_t b1) {
    asm volatile(
        "mma.sync.aligned.m16n8k16.row.col.f32.bf16.bf16.f32 "
        "{%0,%1,%2,%3}, {%4,%5,%6,%7}, {%8,%9}, {%0,%1,%2,%3};"
        : "+f"(d[0]), "+f"(d[1]), "+f"(d[2]), "+f"(d[3])
        : "r"(a[0]), "r"(a[1]), "r"(a[2]), "r"(a[3]), "r"(b0), "r"(b1));
}

// ---------------------------------------------------------------------------
// bf16 4-term split prep: exact x.e up to fp32 accumulation noise
__global__ void prep_x_kernel(const float* __restrict__ x) {
    int i = blockIdx.x * blockDim.x + threadIdx.x;
    if (i >= NTOK * DDIM) return;
    int t = i >> 8, c = i & 255;
    float v = x[i];
    __nv_bfloat16 h = __float2bfloat16(v);
    __nv_bfloat16 l = __float2bfloat16(v - __bfloat162float(h));
    size_t base = (size_t)t * KBIG;
    g_Abig[base + c]       = h;
    g_Abig[base + 256 + c] = h;
    g_Abig[base + 512 + c] = l;
    g_Abig[base + 768 + c] = l;
}
__global__ void prep_e_kernel(const float* __restrict__ e) {
    int i = blockIdx.x * blockDim.x + threadIdx.x;
    if (i >= VDIM * DDIM) return;
    int vrow = i >> 8, c = i & 255;
    float v = e[i];
    __nv_bfloat16 h = __float2bfloat16(v);
    __nv_bfloat16 l = __float2bfloat16(v - __bfloat162float(h));
    size_t base = (size_t)vrow * KBIG;
    g_Bbig[base + c]       = h;
    g_Bbig[base + 256 + c] = l;
    g_Bbig[base + 512 + c] = h;
    g_Bbig[base + 768 + c] = l;
}

// 0.5*||e||^2 per codebook row (one warp per row)
__global__ void en2_kernel(const float* __restrict__ embed) {
    int warp = (blockIdx.x * blockDim.x + threadIdx.x) >> 5;
    int lane = threadIdx.x & 31;
    if (warp >= VDIM) return;
    const float* row = embed + (size_t)warp * DDIM;
    float s = 0.f;
#pragma unroll
    for (int j = 0; j < 8; j++) { float x = row[lane + 32 * j]; s += x * x; }
#pragma unroll
    for (int o = 16; o; o >>= 1) s += __shfl_xor_sync(0xffffffffu, s, o);
    if (lane == 0) g_en2[warp] = 0.5f * s;
}

__global__ void zero_kernel() {
    int i = blockIdx.x * blockDim.x + threadIdx.x;
    int stride = gridDim.x * blockDim.x;
    for (int idx = i; idx < VDIM * DDIM; idx += stride) g_sums[idx] = 0.f;
    for (int idx = i; idx < VDIM; idx += stride) g_counts[idx] = 0.f;
}

// ---------------------------------------------------------------------------
// Tensor-core (mma.sync bf16) fused distance-GEMM + argmin.
// A tile (64 tokens x K=1024) resident in smem; B streamed in 64-K chunks
// through a 3-stage cp.async ring. score = 0.5||e||^2 - x.e
__global__ __launch_bounds__(TPB, 1)
void argmin_mma_kernel() {
    extern __shared__ char smem[];
    const uint32_t sb = smem_u32(smem);
    const int tid  = threadIdx.x;
    const int lane = tid & 31;
    const int wid  = tid >> 5;
    const int tBase = blockIdx.x * TM;

    float* sen2 = (float*)(smem + SM_EN2);
    float* redv = (float*)(smem + SM_RED);
    int*   redi = (int*)(smem + SM_RED + TM * 4 * 4);

    const int m0 = (wid & 1) * 32;    // warp M offset
    const int n0 = (wid >> 1) * 32;   // warp N offset
    const int warpN = wid >> 1;

    // ---- load resident A tile (64 x 1024 bf16, padded rows) ----
#pragma unroll 4
    for (int i = 0; i < 32; i++) {
        int idx = tid + i * TPB;              // 8192 16B segments
        int r = idx >> 7, j = idx & 127;
        cp16(sb + SM_A + r * A_STRIDE + j * 16,
             g_Abig + (size_t)(tBase + r) * KBIG + j * 8);
    }
    CP_COMMIT();
    CP_WAIT(0);
    __syncthreads();

    // per-thread ldmatrix base addresses
    const uint32_t aBase = sb + SM_A + (m0 + (lane & 15)) * A_STRIDE + ((lane >> 4) << 4);
    const uint32_t bBase = sb + SM_B + (n0 + (lane & 15)) * B_STRIDE + ((lane >> 4) << 4);

    float bestV[4];
    int   bestI[4];
#pragma unroll
    for (int s = 0; s < 4; s++) { bestV[s] = 3.4e38f; bestI[s] = 0; }

    for (int nt = 0; nt < NTILES; nt++) {
        const int vBase = nt * TN;
        if (tid < TN) sen2[tid] = g_en2[vBase + tid];

        // prefetch chunks 0,1
#pragma unroll
        for (int pc = 0; pc < 2; pc++) {
#pragma unroll
            for (int i = 0; i < 4; i++) {
                int idx = tid + i * TPB;          // 1024 segs per chunk
                int r = idx >> 3, j = idx & 7;
                cp16(sb + SM_B + pc * B_BUF + r * B_STRIDE + j * 16,
                     g_Bbig + (size_t)(vBase + r) * KBIG + pc * KCH + j * 8);
            }
            CP_COMMIT();
        }

        float acc[2][4][4];
#pragma unroll
        for (int mb = 0; mb < 2; mb++)
#pragma unroll
            for (int nb = 0; nb < 4; nb++)
#pragma unroll
                for (int r = 0; r < 4; r++) acc[mb][nb][r] = 0.f;

        for (int c = 0; c < NCHUNK; c++) {
            if (c < NCHUNK - 1) CP_WAIT(1); else CP_WAIT(0);
            __syncthreads();
            // prefetch chunk c+2 into ring slot (safe: slot's last reader
            // finished before this barrier)
            if (c + 2 < NCHUNK) {
                int buf2 = (c + 2) % 3;
#pragma unroll
                for (int i = 0; i < 4; i++) {
                    int idx = tid + i * TPB;
                    int r = idx >> 3, j = idx & 7;
                    cp16(sb + SM_B + buf2 * B_BUF + r * B_STRIDE + j * 16,
                         g_Bbig + (size_t)(vBase + r) * KBIG + (c + 2) * KCH + j * 8);
                }
                CP_COMMIT();
            }

            const uint32_t bBuf = bBase + (c % 3) * B_BUF;
            const uint32_t aChunk = aBase + (c * KCH) * 2;
#pragma unroll
            for (int k16 = 0; k16 < 4; k16++) {
                uint32_t a[2][4], b[2][4];
#pragma unroll
                for (int mb = 0; mb < 2; mb++)
                    ldmx4(a[mb], aChunk + mb * (16 * A_STRIDE) + k16 * 32);
#pragma unroll
                for (int nb2 = 0; nb2 < 2; nb2++)
                    ldmx4(b[nb2], bBuf + nb2 * (16 * B_STRIDE) + k16 * 32);
#pragma unroll
                for (int mb = 0; mb < 2; mb++)
#pragma unroll
                    for (int nb = 0; nb < 4; nb++) {
                        uint32_t b0 = (nb & 1) ? b[nb >> 1][1] : b[nb >> 1][0];
                        uint32_t b1 = (nb & 1) ? b[nb >> 1][3] : b[nb >> 1][2];
                        mma16816(acc[mb][nb], a[mb], b0, b1);
                    }
            }
        }

        // epilogue: running argmin over this N-tile
#pragma unroll
        for (int mb = 0; mb < 2; mb++)
#pragma unroll
            for (int nb = 0; nb < 4; nb++)
#pragma unroll
                for (int r = 0; r < 4; r++) {
                    int n = n0 + nb * 8 + ((lane & 3) << 1) + (r & 1);
                    int slot = mb * 2 + (r >> 1);
                    float s = sen2[n] - acc[mb][nb][r];
                    if (s < bestV[slot]) { bestV[slot] = s; bestI[slot] = vBase + n; }
                }
        __syncthreads();   // sen2 + B ring fully consumed before next tile
    }

    // ---- reduce: quad shuffle over n-lanes, then across the 4 n-warps ----
#pragma unroll
    for (int off = 1; off <= 2; off <<= 1) {
#pragma unroll
        for (int s = 0; s < 4; s++) {
            float ov = __shfl_xor_sync(0xffffffffu, bestV[s], off);
            int   oi = __shfl_xor_sync(0xffffffffu, bestI[s], off);
            if (ov < bestV[s] || (ov == bestV[s] && oi < bestI[s])) {
                bestV[s] = ov; bestI[s] = oi;
            }
        }
    }
    if ((lane & 3) == 0) {
#pragma unroll
        for (int s = 0; s < 4; s++) {
            int row = m0 + (s >> 1) * 16 + (s & 1) * 8 + (lane >> 2);
            redv[row * 4 + warpN] = bestV[s];
            redi[row * 4 + warpN] = bestI[s];
        }
    }
    __syncthreads();
    if (tid < TM) {
        float bv = redv[tid * 4];
        int   bi = redi[tid * 4];
#pragma unroll
        for (int j = 1; j < 4; j++) {
            float v = redv[tid * 4 + j];
            int   ii = redi[tid * 4 + j];
            if (v < bv || (v == bv && ii < bi)) { bv = v; bi = ii; }
        }
        g_codes[tBase + tid] = bi;
    }
}

// ---------------------------------------------------------------------------
// Per-token: quantize gather, codes, EMA scatter
__global__ void scatter_kernel(const float* __restrict__ input,
                               const float* __restrict__ embed,
                               float* __restrict__ out) {
    int t = blockIdx.x;
    int d = threadIdx.x;
    int c = g_codes[t];
    out[OFF_Q + (size_t)t * DDIM + d] = embed[(size_t)c * DDIM + d];
    atomicAdd(&g_sums[(size_t)c * DDIM + d], input[(size_t)t * DDIM + d]);
    if (d == 0) {
        atomicAdd(&g_counts[c], 1.0f);
        out[OFF_CODE + t] = (float)c;
    }
}

__global__ void finalize_kernel(const float* __restrict__ cluster_size,
                                const float* __restrict__ embed_avg,
                                float* __restrict__ out) {
    int idx = blockIdx.x * blockDim.x + threadIdx.x;
    if (idx >= VDIM * DDIM) return;
    int v = idx >> 8;
    float ncs = cluster_size[v] * 0.99f + g_counts[v] * 0.01f;
    float avg = embed_avg[idx] * 0.99f + (g_sums[idx] * (1.0f / TVAL)) * 0.01f;
    out[OFF_NEA + idx] = avg;
    out[OFF_NE + idx]  = avg / (ncs + 1e-5f);
    if ((idx & 255) == 0) out[OFF_NCS + v] = ncs;
}

// ---------------------------------------------------------------------------
extern "C" void kernel_launch(void* const* d_in, const int* in_sizes, int n_in,
                              void* d_out, int out_size) {
    const float* input        = (const float*)d_in[0];
    const float* embed        = (const float*)d_in[1];
    const float* cluster_size = (const float*)d_in[2];
    const float* embed_avg    = (const float*)d_in[3];
    float* out = (float*)d_out;

    cudaFuncSetAttribute(argmin_mma_kernel,
                         cudaFuncAttributeMaxDynamicSharedMemorySize, SM_TOTAL);

    prep_x_kernel<<<(NTOK * DDIM) / 256, 256>>>(input);
    prep_e_kernel<<<(VDIM * DDIM) / 256, 256>>>(embed);
    en2_kernel<<<VDIM / 8, 256>>>(embed);
    zero_kernel<<<2048, 256>>>();
    argmin_mma_kernel<<<NTOK / TM, TPB, SM_TOTAL>>>();
    scatter_kernel<<<NTOK, DDIM>>>(input, embed, out);
    finalize_kernel<<<(VDIM * DDIM + 255) / 256, 256>>>(cluster_size, embed_avg, out);
}

// round 6
// speedup vs baseline: 2.6061x; 1.2949x over previous
#include <cuda_runtime.h>
#include <cuda_fp16.h>
#include <cstdint>

// Problem dims (fixed per reference setup_inputs)
#define NTOK 16384   // B*T
#define DDIM 256
#define VDIM 8192
#define TVAL 2048

// fp16 3-term split: x.e = xh.eh + xh.el + xl.eh  (+ dropped xl.el ~ 2^-22)
// Packed operand storage: A = [xh|xl] (512), B = [eh|el] (512).
#define KPACK 512

// Argmin GEMM tiling
#define TM 128       // tokens per CTA (A resident in smem)
#define TN 128       // codes per N-tile
#define KCH 64       // K elems per streamed B chunk
#define NCHUNK 12    // 3 terms x 4 chunks of 64
#define NTILES (VDIM / TN)    // 64
#define TPB 256               // 8 warps: 4 (M) x 2 (N), warp tile 32x64

// Smem layout (bytes)
#define A_PAD_E 520                  // 512 + 8 elems -> 1040B stride (odd segs)
#define A_STRIDE (A_PAD_E * 2)       // 1040
#define B_PAD_E 72                   // 64 + 8 elems -> 144B stride (odd segs)
#define B_STRIDE (B_PAD_E * 2)       // 144
#define SM_A 0
#define SM_B (TM * A_STRIDE)                 // 133120
#define B_BUF (TN * B_STRIDE)                // 18432
#define SM_EN2 (SM_B + 3 * B_BUF)            // 188416
#define SM_RED (SM_EN2 + TN * 4)             // 188928
#define SM_TOTAL (SM_RED + TM * 2 * 8)       // 190976

// Output layout (concatenated flattened, float32)
#define OFF_Q    0
#define OFF_CODE 4194304
#define OFF_NE   4210688
#define OFF_NCS  6307840
#define OFF_NEA  6316032

// ---------------------------------------------------------------------------
// Device scratch (no allocations allowed)
__device__ __half g_A[(size_t)NTOK * KPACK];
__device__ __half g_B[(size_t)VDIM * KPACK];
__device__ float g_sums[VDIM * DDIM];
__device__ float g_counts[VDIM];
__device__ float g_en2[VDIM];
__device__ int   g_codes[NTOK];

// ---------------------------------------------------------------------------
__device__ __forceinline__ uint32_t smem_u32(const void* p) {
    uint32_t a;
    asm("{ .reg .u64 t; cvta.to.shared.u64 t, %1; cvt.u32.u64 %0, t; }"
        : "=r"(a) : "l"(p));
    return a;
}
__device__ __forceinline__ void cp16(uint32_t dst, const void* src) {
    asm volatile("cp.async.cg.shared.global [%0], [%1], 16;"
                 :: "r"(dst), "l"(src) : "memory");
}
#define CP_COMMIT() asm volatile("cp.async.commit_group;" ::: "memory")
#define CP_WAIT(n)  asm volatile("cp.async.wait_group %0;" :: "n"(n) : "memory")

__device__ __forceinline__ void ldmx4(uint32_t (&r)[4], uint32_t addr) {
    asm volatile("ldmatrix.sync.aligned.m8n8.x4.shared.b16 {%0,%1,%2,%3}, [%4];"
                 : "=r"(r[0]), "=r"(r[1]), "=r"(r[2]), "=r"(r[3]) : "r"(addr));
}
__device__ __forceinline__ void mma16816(float (&d)[4], const uint32_t (&a)[4],
                                         uint32_t b0, uint32_t b1) {
    asm volatile(
        "mma.sync.aligned.m16n8k16.row.col.f32.f16.f16.f32 "
        "{%0,%1,%2,%3}, {%4,%5,%6,%7}, {%8,%9}, {%0,%1,%2,%3};"
        : "+f"(d[0]), "+f"(d[1]), "+f"(d[2]), "+f"(d[3])
        : "r"(a[0]), "r"(a[1]), "r"(a[2]), "r"(a[3]), "r"(b0), "r"(b1));
}

// ---------------------------------------------------------------------------
// fp16 2-level split prep (packed halves)
__global__ void prep_x_kernel(const float* __restrict__ x) {
    int i = blockIdx.x * blockDim.x + threadIdx.x;
    if (i >= NTOK * DDIM) return;
    int t = i >> 8, c = i & 255;
    float v = x[i];
    __half h = __float2half(v);
    __half l = __float2half(v - __half2float(h));
    size_t base = (size_t)t * KPACK;
    g_A[base + c]       = h;
    g_A[base + 256 + c] = l;
}
__global__ void prep_e_kernel(const float* __restrict__ e) {
    int i = blockIdx.x * blockDim.x + threadIdx.x;
    if (i >= VDIM * DDIM) return;
    int vrow = i >> 8, c = i & 255;
    float v = e[i];
    __half h = __float2half(v);
    __half l = __float2half(v - __half2float(h));
    size_t base = (size_t)vrow * KPACK;
    g_B[base + c]       = h;
    g_B[base + 256 + c] = l;
}

// 0.5*||e||^2 per codebook row (one warp per row, fp32)
__global__ void en2_kernel(const float* __restrict__ embed) {
    int warp = (blockIdx.x * blockDim.x + threadIdx.x) >> 5;
    int lane = threadIdx.x & 31;
    if (warp >= VDIM) return;
    const float* row = embed + (size_t)warp * DDIM;
    float s = 0.f;
#pragma unroll
    for (int j = 0; j < 8; j++) { float x = row[lane + 32 * j]; s += x * x; }
#pragma unroll
    for (int o = 16; o; o >>= 1) s += __shfl_xor_sync(0xffffffffu, s, o);
    if (lane == 0) g_en2[warp] = 0.5f * s;
}

__global__ void zero_kernel() {
    int i = blockIdx.x * blockDim.x + threadIdx.x;
    int stride = gridDim.x * blockDim.x;
    for (int idx = i; idx < VDIM * DDIM; idx += stride) g_sums[idx] = 0.f;
    for (int idx = i; idx < VDIM; idx += stride) g_counts[idx] = 0.f;
}

// ---------------------------------------------------------------------------
// mma.sync fp16 fused distance-GEMM + argmin.
// A packed tile (128 tokens x 512) resident; B streamed in 64-K chunks via a
// 3-stage cp.async ring. 3 term-pairings of the packed halves give the
// fp16-split exact dot product. score = 0.5||e||^2 - x.e
__global__ __launch_bounds__(TPB, 1)
void argmin_mma_kernel() {
    extern __shared__ char smem[];
    const uint32_t sb = smem_u32(smem);
    const int tid  = threadIdx.x;
    const int lane = tid & 31;
    const int wid  = tid >> 5;
    const int tBase = blockIdx.x * TM;

    float* sen2 = (float*)(smem + SM_EN2);
    float* redv = (float*)(smem + SM_RED);
    int*   redi = (int*)(smem + SM_RED + TM * 2 * 4);

    const int warpM = wid & 3;
    const int warpN = wid >> 2;
    const int m0 = warpM * 32;
    const int n0 = warpN * 64;

    // ---- load resident packed A tile (128 x 512 fp16, padded rows) ----
#pragma unroll 4
    for (int i = 0; i < 32; i++) {
        int idx = tid + i * TPB;              // 8192 16B segments
        int r = idx >> 6, j = idx & 63;       // 64 segs per 512-elem row
        cp16(sb + SM_A + r * A_STRIDE + j * 16,
             g_A + (size_t)(tBase + r) * KPACK + j * 8);
    }
    CP_COMMIT();
    CP_WAIT(0);
    __syncthreads();

    // per-thread ldmatrix base addresses
    const uint32_t aBase = sb + SM_A + (m0 + (lane & 15)) * A_STRIDE + ((lane >> 4) << 4);
    const uint32_t bBase = sb + SM_B + (n0 + (lane & 15)) * B_STRIDE + ((lane >> 4) << 4);

    float bestV[4];
    int   bestI[4];
#pragma unroll
    for (int s = 0; s < 4; s++) { bestV[s] = 3.4e38f; bestI[s] = 0; }

    for (int nt = 0; nt < NTILES; nt++) {
        const int vBase = nt * TN;
        if (tid < TN) sen2[tid] = g_en2[vBase + tid];

        // prefetch chunks 0,1  (term/chunk schedule: term = kc/4, kk = kc%4;
        //  aoff = (term==2?256:0)+kk*64 ; boff = (term==1?256:0)+kk*64)
        // B chunk = 128 rows x 64 elems = 8 x 16B segs per row = 1024 segs.
#pragma unroll
        for (int pc = 0; pc < 2; pc++) {
            int boff = pc * 64;  // kc=0,1 -> term 0
#pragma unroll
            for (int i = 0; i < 4; i++) {
                int idx = tid + i * TPB;          // 1024 segs per chunk
                int r = idx >> 3, j = idx & 7;
                cp16(sb + SM_B + pc * B_BUF + r * B_STRIDE + j * 16,
                     g_B + (size_t)(vBase + r) * KPACK + boff + j * 8);
            }
            CP_COMMIT();
        }

        float acc[2][8][4];
#pragma unroll
        for (int mb = 0; mb < 2; mb++)
#pragma unroll
            for (int nb = 0; nb < 8; nb++)
#pragma unroll
                for (int r = 0; r < 4; r++) acc[mb][nb][r] = 0.f;

        for (int kc = 0; kc < NCHUNK; kc++) {
            if (kc < NCHUNK - 1) CP_WAIT(1); else CP_WAIT(0);
            __syncthreads();
            // prefetch chunk kc+2 (its ring slot was last read at iter kc-1,
            // which completed before this barrier)
            if (kc + 2 < NCHUNK) {
                int c2 = kc + 2;
                int term2 = c2 >> 2, kk2 = c2 & 3;
                int boff2 = ((term2 == 1) ? 256 : 0) + kk2 * 64;
                int buf2 = c2 % 3;
#pragma unroll
                for (int i = 0; i < 4; i++) {
                    int idx = tid + i * TPB;
                    int r = idx >> 3, j = idx & 7;
                    cp16(sb + SM_B + buf2 * B_BUF + r * B_STRIDE + j * 16,
                         g_B + (size_t)(vBase + r) * KPACK + boff2 + j * 8);
                }
                CP_COMMIT();
            }

            const int term = kc >> 2, kk = kc & 3;
            const int aoff = ((term == 2) ? 256 : 0) + kk * 64;
            const uint32_t bBuf = bBase + (kc % 3) * B_BUF;
            const uint32_t aChunk = aBase + aoff * 2;

#pragma unroll
            for (int k16 = 0; k16 < 4; k16++) {
                uint32_t a[2][4], b[4][4];
#pragma unroll
                for (int mb = 0; mb < 2; mb++)
                    ldmx4(a[mb], aChunk + mb * (16 * A_STRIDE) + k16 * 32);
#pragma unroll
                for (int g = 0; g < 4; g++)
                    ldmx4(b[g], bBuf + g * (16 * B_STRIDE) + k16 * 32);
#pragma unroll
                for (int mb = 0; mb < 2; mb++)
#pragma unroll
                    for (int nb = 0; nb < 8; nb++) {
                        uint32_t b0 = (nb & 1) ? b[nb >> 1][1] : b[nb >> 1][0];
                        uint32_t b1 = (nb & 1) ? b[nb >> 1][3] : b[nb >> 1][2];
                        mma16816(acc[mb][nb], a[mb], b0, b1);
                    }
            }
        }

        // epilogue: running argmin over this N-tile
#pragma unroll
        for (int mb = 0; mb < 2; mb++)
#pragma unroll
            for (int nb = 0; nb < 8; nb++)
#pragma unroll
                for (int r = 0; r < 4; r++) {
                    int n = n0 + nb * 8 + ((lane & 3) << 1) + (r & 1);
                    int slot = mb * 2 + (r >> 1);
                    float s = sen2[n] - acc[mb][nb][r];
                    if (s < bestV[slot]) { bestV[slot] = s; bestI[slot] = vBase + n; }
                }
        __syncthreads();   // sen2 + B ring fully consumed before next tile
    }

    // ---- reduce: quad shuffle over n-lanes, then across the 2 n-warps ----
#pragma unroll
    for (int off = 1; off <= 2; off <<= 1) {
#pragma unroll
        for (int s = 0; s < 4; s++) {
            float ov = __shfl_xor_sync(0xffffffffu, bestV[s], off);
            int   oi = __shfl_xor_sync(0xffffffffu, bestI[s], off);
            if (ov < bestV[s] || (ov == bestV[s] && oi < bestI[s])) {
                bestV[s] = ov; bestI[s] = oi;
            }
        }
    }
    if ((lane & 3) == 0) {
#pragma unroll
        for (int s = 0; s < 4; s++) {
            int row = m0 + (s >> 1) * 16 + (s & 1) * 8 + (lane >> 2);
            redv[row * 2 + warpN] = bestV[s];
            redi[row * 2 + warpN] = bestI[s];
        }
    }
    __syncthreads();
    if (tid < TM) {
        float v0 = redv[tid * 2 + 0], v1 = redv[tid * 2 + 1];
        int   i0 = redi[tid * 2 + 0], i1 = redi[tid * 2 + 1];
        bool take1 = (v1 < v0) || (v1 == v0 && i1 < i0);
        g_codes[tBase + tid] = take1 ? i1 : i0;
    }
}

// ---------------------------------------------------------------------------
// Per-token: quantize gather, codes, EMA scatter
__global__ void scatter_kernel(const float* __restrict__ input,
                               const float* __restrict__ embed,
                               float* __restrict__ out) {
    int t = blockIdx.x;
    int d = threadIdx.x;
    int c = g_codes[t];
    out[OFF_Q + (size_t)t * DDIM + d] = embed[(size_t)c * DDIM + d];
    atomicAdd(&g_sums[(size_t)c * DDIM + d], input[(size_t)t * DDIM + d]);
    if (d == 0) {
        atomicAdd(&g_counts[c], 1.0f);
        out[OFF_CODE + t] = (float)c;
    }
}

__global__ void finalize_kernel(const float* __restrict__ cluster_size,
                                const float* __restrict__ embed_avg,
                                float* __restrict__ out) {
    int idx = blockIdx.x * blockDim.x + threadIdx.x;
    if (idx >= VDIM * DDIM) return;
    int v = idx >> 8;
    float ncs = cluster_size[v] * 0.99f + g_counts[v] * 0.01f;
    float avg = embed_avg[idx] * 0.99f + (g_sums[idx] * (1.0f / TVAL)) * 0.01f;
    out[OFF_NEA + idx] = avg;
    out[OFF_NE + idx]  = avg / (ncs + 1e-5f);
    if ((idx & 255) == 0) out[OFF_NCS + v] = ncs;
}

// ---------------------------------------------------------------------------
extern "C" void kernel_launch(void* const* d_in, const int* in_sizes, int n_in,
                              void* d_out, int out_size) {
    const float* input        = (const float*)d_in[0];
    const float* embed        = (const float*)d_in[1];
    const float* cluster_size = (const float*)d_in[2];
    const float* embed_avg    = (const float*)d_in[3];
    float* out = (float*)d_out;

    cudaFuncSetAttribute(argmin_mma_kernel,
                         cudaFuncAttributeMaxDynamicSharedMemorySize, SM_TOTAL);

    prep_x_kernel<<<(NTOK * DDIM) / 256, 256>>>(input);
    prep_e_kernel<<<(VDIM * DDIM) / 256, 256>>>(embed);
    en2_kernel<<<VDIM / 8, 256>>>(embed);
    zero_kernel<<<2048, 256>>>();
    argmin_mma_kernel<<<NTOK / TM, TPB, SM_TOTAL>>>();
    scatter_kernel<<<NTOK, DDIM>>>(input, embed, out);
    finalize_kernel<<<(VDIM * DDIM + 255) / 256, 256>>>(cluster_size, embed_avg, out);
}

// round 7
// speedup vs baseline: 2.8776x; 1.1042x over previous
#include <cuda_runtime.h>
#include <cuda_fp16.h>
#include <cstdint>

// Problem dims (fixed per reference setup_inputs)
#define NTOK 16384   // B*T
#define DDIM 256
#define VDIM 8192
#define TVAL 2048

// fp16 3-term split: x.e = xh.eh + xh.el + xl.eh  (+ dropped xl.el ~ 2^-22)
// Packed operand storage: A = [xh|xl] (512), B = [eh|el] (512).
#define KPACK 512

// Argmin GEMM tiling
#define TM 128       // tokens per CTA (A resident in smem)
#define TN 128       // codes per N-tile
#define KCH 128      // K elems per streamed B chunk
#define NCHUNK 6     // 3 terms x 2 chunks of 128
#define NTILES (VDIM / TN)    // 64
#define TPB 256               // 8 warps: 4 (M) x 2 (N), warp tile 32x64

// Smem layout (bytes)
#define A_PAD_E 520                  // 512 + 8 elems -> 1040B stride (odd segs)
#define A_STRIDE (A_PAD_E * 2)       // 1040
#define B_PAD_E 136                  // 128 + 8 elems -> 272B stride (odd segs)
#define B_STRIDE (B_PAD_E * 2)       // 272
#define SM_A 0
#define SM_B (TM * A_STRIDE)                 // 133120
#define B_BUF (TN * B_STRIDE)                // 34816
#define SM_EN2 (SM_B + 2 * B_BUF)            // 202752
#define SM_RED (SM_EN2 + TN * 4)             // 203264
#define SM_TOTAL (SM_RED + TM * 2 * 8)       // 205312

// Output layout (concatenated flattened, float32)
#define OFF_Q    0
#define OFF_CODE 4194304
#define OFF_NE   4210688
#define OFF_NCS  6307840
#define OFF_NEA  6316032

// ---------------------------------------------------------------------------
// Device scratch (no allocations allowed)
__device__ __half g_A[(size_t)NTOK * KPACK];
__device__ __half g_B[(size_t)VDIM * KPACK];
__device__ float g_sums[VDIM * DDIM];
__device__ float g_counts[VDIM];
__device__ float g_en2[VDIM];
__device__ int   g_codes[NTOK];

// ---------------------------------------------------------------------------
__device__ __forceinline__ uint32_t smem_u32(const void* p) {
    uint32_t a;
    asm("{ .reg .u64 t; cvta.to.shared.u64 t, %1; cvt.u32.u64 %0, t; }"
        : "=r"(a) : "l"(p));
    return a;
}
__device__ __forceinline__ void cp16(uint32_t dst, const void* src) {
    asm volatile("cp.async.cg.shared.global [%0], [%1], 16;"
                 :: "r"(dst), "l"(src) : "memory");
}
#define CP_COMMIT() asm volatile("cp.async.commit_group;" ::: "memory")
#define CP_WAIT(n)  asm volatile("cp.async.wait_group %0;" :: "n"(n) : "memory")

__device__ __forceinline__ void ldmx4(uint32_t (&r)[4], uint32_t addr) {
    asm volatile("ldmatrix.sync.aligned.m8n8.x4.shared.b16 {%0,%1,%2,%3}, [%4];"
                 : "=r"(r[0]), "=r"(r[1]), "=r"(r[2]), "=r"(r[3]) : "r"(addr));
}
__device__ __forceinline__ void mma16816(float (&d)[4], const uint32_t (&a)[4],
                                         uint32_t b0, uint32_t b1) {
    asm volatile(
        "mma.sync.aligned.m16n8k16.row.col.f32.f16.f16.f32 "
        "{%0,%1,%2,%3}, {%4,%5,%6,%7}, {%8,%9}, {%0,%1,%2,%3};"
        : "+f"(d[0]), "+f"(d[1]), "+f"(d[2]), "+f"(d[3])
        : "r"(a[0]), "r"(a[1]), "r"(a[2]), "r"(a[3]), "r"(b0), "r"(b1));
}

// ---------------------------------------------------------------------------
// fp16 2-level split prep (packed halves)
__global__ void prep_x_kernel(const float* __restrict__ x) {
    int i = blockIdx.x * blockDim.x + threadIdx.x;
    if (i >= NTOK * DDIM) return;
    int t = i >> 8, c = i & 255;
    float v = x[i];
    __half h = __float2half(v);
    __half l = __float2half(v - __half2float(h));
    size_t base = (size_t)t * KPACK;
    g_A[base + c]       = h;
    g_A[base + 256 + c] = l;
}

// prep_e fused with 0.5*||e||^2 (one warp per codebook row)
__global__ void prep_e_kernel(const float* __restrict__ e) {
    int warp = (blockIdx.x * blockDim.x + threadIdx.x) >> 5;
    int lane = threadIdx.x & 31;
    if (warp >= VDIM) return;
    const float* row = e + (size_t)warp * DDIM;
    size_t base = (size_t)warp * KPACK;
    float s = 0.f;
#pragma unroll
    for (int j = 0; j < 8; j++) {
        int c = lane + 32 * j;
        float v = row[c];
        s += v * v;
        __half h = __float2half(v);
        __half l = __float2half(v - __half2float(h));
        g_B[base + c]       = h;
        g_B[base + 256 + c] = l;
    }
#pragma unroll
    for (int o = 16; o; o >>= 1) s += __shfl_xor_sync(0xffffffffu, s, o);
    if (lane == 0) g_en2[warp] = 0.5f * s;
}

__global__ void zero_kernel() {
    int i = blockIdx.x * blockDim.x + threadIdx.x;
    int stride = gridDim.x * blockDim.x;
    for (int idx = i; idx < VDIM * DDIM; idx += stride) g_sums[idx] = 0.f;
    for (int idx = i; idx < VDIM; idx += stride) g_counts[idx] = 0.f;
}

// ---------------------------------------------------------------------------
// chunk schedule helpers: term = kc/2, kk = kc%2
__device__ __forceinline__ int chunk_boff(int kc) {
    int term = kc >> 1, kk = kc & 1;
    return ((term == 1) ? 256 : 0) + kk * KCH;
}
__device__ __forceinline__ int chunk_aoff(int kc) {
    int term = kc >> 1, kk = kc & 1;
    return ((term == 2) ? 256 : 0) + kk * KCH;
}

// mma.sync fp16 fused distance-GEMM + argmin.
// A packed tile (128 x 512) resident; B streamed in 128-K chunks via a
// 2-stage cp.async ring with cross-tile prefetch. Fragments double-buffered
// in registers across k16 steps. score = 0.5||e||^2 - x.e
__global__ __launch_bounds__(TPB, 1)
void argmin_mma_kernel() {
    extern __shared__ char smem[];
    const uint32_t sb = smem_u32(smem);
    const int tid  = threadIdx.x;
    const int lane = tid & 31;
    const int wid  = tid >> 5;
    const int tBase = blockIdx.x * TM;

    float* sen2 = (float*)(smem + SM_EN2);
    float* redv = (float*)(smem + SM_RED);
    int*   redi = (int*)(smem + SM_RED + TM * 2 * 4);

    const int warpM = wid & 3;
    const int warpN = wid >> 2;
    const int m0 = warpM * 32;
    const int n0 = warpN * 64;

    // ---- load resident packed A tile (128 x 512 fp16, padded rows) ----
#pragma unroll 4
    for (int i = 0; i < 32; i++) {
        int idx = tid + i * TPB;              // 8192 16B segments
        int r = idx >> 6, j = idx & 63;       // 64 segs per 512-elem row
        cp16(sb + SM_A + r * A_STRIDE + j * 16,
             g_A + (size_t)(tBase + r) * KPACK + j * 8);
    }
    CP_COMMIT();

    // B chunk loader: 128 rows x 128 elems = 16 segs/row = 2048 segs
    auto loadB = [&](int buf, int vB, int boff) {
#pragma unroll
        for (int i = 0; i < 8; i++) {
            int idx = tid + i * TPB;
            int r = idx >> 4, j = idx & 15;
            cp16(sb + SM_B + buf * B_BUF + r * B_STRIDE + j * 16,
                 g_B + (size_t)(vB + r) * KPACK + boff + j * 8);
        }
        CP_COMMIT();
    };

    // prefetch tile 0 / chunk 0
    loadB(0, 0, chunk_boff(0));
    CP_WAIT(1);              // A tile ready
    __syncthreads();

    // per-thread ldmatrix base addresses
    const uint32_t aBase = sb + SM_A + (m0 + (lane & 15)) * A_STRIDE + ((lane >> 4) << 4);
    const uint32_t bBase = sb + SM_B + (n0 + (lane & 15)) * B_STRIDE + ((lane >> 4) << 4);

    float bestV[4];
    int   bestI[4];
#pragma unroll
    for (int s = 0; s < 4; s++) { bestV[s] = 3.4e38f; bestI[s] = 0; }

    for (int nt = 0; nt < NTILES; nt++) {
        const int vBase = nt * TN;
        if (tid < TN) sen2[tid] = g_en2[vBase + tid];

        float acc[2][8][4];
#pragma unroll
        for (int mb = 0; mb < 2; mb++)
#pragma unroll
            for (int nb = 0; nb < 8; nb++)
#pragma unroll
                for (int r = 0; r < 4; r++) acc[mb][nb][r] = 0.f;

        for (int kc = 0; kc < NCHUNK; kc++) {
            CP_WAIT(0);        // chunk kc resident
            __syncthreads();   // all warps see it; prev buf fully consumed
            // prefetch next chunk (same or next tile) into the other buffer
            if (kc < NCHUNK - 1) {
                loadB((kc + 1) & 1, vBase, chunk_boff(kc + 1));
            } else if (nt < NTILES - 1) {
                loadB((kc + 1) & 1, vBase + TN, chunk_boff(0));
            }

            const uint32_t aChunk = aBase + chunk_aoff(kc) * 2;
            const uint32_t bBuf = bBase + (kc & 1) * B_BUF;

            // fragment double-buffer across the 8 k16 steps
            uint32_t a[2][2][4], b[2][4][4];
#pragma unroll
            for (int mb = 0; mb < 2; mb++)
                ldmx4(a[0][mb], aChunk + mb * (16 * A_STRIDE));
#pragma unroll
            for (int g = 0; g < 4; g++)
                ldmx4(b[0][g], bBuf + g * (16 * B_STRIDE));

#pragma unroll
            for (int k16 = 0; k16 < 8; k16++) {
                const int cur = k16 & 1, nxt = cur ^ 1;
                if (k16 < 7) {
#pragma unroll
                    for (int mb = 0; mb < 2; mb++)
                        ldmx4(a[nxt][mb],
                              aChunk + mb * (16 * A_STRIDE) + (k16 + 1) * 32);
#pragma unroll
                    for (int g = 0; g < 4; g++)
                        ldmx4(b[nxt][g],
                              bBuf + g * (16 * B_STRIDE) + (k16 + 1) * 32);
                }
#pragma unroll
                for (int mb = 0; mb < 2; mb++)
#pragma unroll
                    for (int nb = 0; nb < 8; nb++) {
                        uint32_t b0 = (nb & 1) ? b[cur][nb >> 1][1] : b[cur][nb >> 1][0];
                        uint32_t b1 = (nb & 1) ? b[cur][nb >> 1][3] : b[cur][nb >> 1][2];
                        mma16816(acc[mb][nb], a[cur][mb], b0, b1);
                    }
            }
        }

        // epilogue: running argmin over this N-tile
#pragma unroll
        for (int mb = 0; mb < 2; mb++)
#pragma unroll
            for (int nb = 0; nb < 8; nb++)
#pragma unroll
                for (int r = 0; r < 4; r++) {
                    int n = n0 + nb * 8 + ((lane & 3) << 1) + (r & 1);
                    int slot = mb * 2 + (r >> 1);
                    float s = sen2[n] - acc[mb][nb][r];
                    if (s < bestV[slot]) { bestV[slot] = s; bestI[slot] = vBase + n; }
                }
        __syncthreads();   // sen2 fully consumed before next tile's write
    }

    // ---- reduce: quad shuffle over n-lanes, then across the 2 n-warps ----
#pragma unroll
    for (int off = 1; off <= 2; off <<= 1) {
#pragma unroll
        for (int s = 0; s < 4; s++) {
            float ov = __shfl_xor_sync(0xffffffffu, bestV[s], off);
            int   oi = __shfl_xor_sync(0xffffffffu, bestI[s], off);
            if (ov < bestV[s] || (ov == bestV[s] && oi < bestI[s])) {
                bestV[s] = ov; bestI[s] = oi;
            }
        }
    }
    if ((lane & 3) == 0) {
#pragma unroll
        for (int s = 0; s < 4; s++) {
            int row = m0 + (s >> 1) * 16 + (s & 1) * 8 + (lane >> 2);
            redv[row * 2 + warpN] = bestV[s];
            redi[row * 2 + warpN] = bestI[s];
        }
    }
    __syncthreads();
    if (tid < TM) {
        float v0 = redv[tid * 2 + 0], v1 = redv[tid * 2 + 1];
        int   i0 = redi[tid * 2 + 0], i1 = redi[tid * 2 + 1];
        bool take1 = (v1 < v0) || (v1 == v0 && i1 < i0);
        g_codes[tBase + tid] = take1 ? i1 : i0;
    }
}

// ---------------------------------------------------------------------------
// Per-token: quantize gather, codes, EMA scatter
__global__ void scatter_kernel(const float* __restrict__ input,
                               const float* __restrict__ embed,
                               float* __restrict__ out) {
    int t = blockIdx.x;
    int d = threadIdx.x;
    int c = g_codes[t];
    out[OFF_Q + (size_t)t * DDIM + d] = embed[(size_t)c * DDIM + d];
    atomicAdd(&g_sums[(size_t)c * DDIM + d], input[(size_t)t * DDIM + d]);
    if (d == 0) {
        atomicAdd(&g_counts[c], 1.0f);
        out[OFF_CODE + t] = (float)c;
    }
}

__global__ void finalize_kernel(const float* __restrict__ cluster_size,
                                const float* __restrict__ embed_avg,
                                float* __restrict__ out) {
    int idx = blockIdx.x * blockDim.x + threadIdx.x;
    if (idx >= VDIM * DDIM) return;
    int v = idx >> 8;
    float ncs = cluster_size[v] * 0.99f + g_counts[v] * 0.01f;
    float avg = embed_avg[idx] * 0.99f + (g_sums[idx] * (1.0f / TVAL)) * 0.01f;
    out[OFF_NEA + idx] = avg;
    out[OFF_NE + idx]  = avg / (ncs + 1e-5f);
    if ((idx & 255) == 0) out[OFF_NCS + v] = ncs;
}

// ---------------------------------------------------------------------------
extern "C" void kernel_launch(void* const* d_in, const int* in_sizes, int n_in,
                              void* d_out, int out_size) {
    const float* input        = (const float*)d_in[0];
    const float* embed        = (const float*)d_in[1];
    const float* cluster_size = (const float*)d_in[2];
    const float* embed_avg    = (const float*)d_in[3];
    float* out = (float*)d_out;

    cudaFuncSetAttribute(argmin_mma_kernel,
                         cudaFuncAttributeMaxDynamicSharedMemorySize, SM_TOTAL);

    // argmin is the 4th launch so ncu's fixed-skip capture profiles it
    prep_x_kernel<<<(NTOK * DDIM) / 256, 256>>>(input);
    prep_e_kernel<<<VDIM / 8, 256>>>(embed);
    zero_kernel<<<2048, 256>>>();
    argmin_mma_kernel<<<NTOK / TM, TPB, SM_TOTAL>>>();
    scatter_kernel<<<NTOK, DDIM>>>(input, embed, out);
    finalize_kernel<<<(VDIM * DDIM + 255) / 256, 256>>>(cluster_size, embed_avg, out);
}